// round 1
// baseline (speedup 1.0000x reference)
#include <cuda_runtime.h>
#include <mma.h>
#include <math.h>

using namespace nvcuda;

#define BATCH 4
#define SEQ   2048
#define DIM   1024

// Tiling
#define BM 128
#define BN 64
#define BK 16
#define PADA 8   // As ld = 24 floats (96B rows, 32B aligned, mult of 4)
#define PADB 8   // Bs ld = 72 floats (288B rows)

// Scratch (allocations are forbidden; use __device__ globals)
__device__ float g_Q[(size_t)BATCH * SEQ * DIM];
__device__ float g_K[(size_t)BATCH * SEQ * DIM];
__device__ float g_V[(size_t)BATCH * SEQ * DIM];
__device__ float g_S[(size_t)BATCH * SEQ * SEQ];

// ---------------------------------------------------------------------------
// NN GEMM: C[M,N] = A[M,K] @ B[K,N], both row-major, fp32 in/out, tf32 mma.
// causal!=0 limits K loop to (blockRow_end) — valid because P is exactly zero
// above the diagonal after softmax.
// ---------------------------------------------------------------------------
__global__ void __launch_bounds__(256) gemm_nn(
    const float* __restrict__ A, const float* __restrict__ B,
    float* __restrict__ C,
    int M, int N, int K,
    long sA, long sB, long sC, int causal)
{
    A += (long)blockIdx.z * sA;
    B += (long)blockIdx.z * sB;
    C += (long)blockIdx.z * sC;

    const int i0 = blockIdx.y * BM;
    const int j0 = blockIdx.x * BN;
    const int kEnd = causal ? ((i0 + BM < K) ? (i0 + BM) : K) : K;

    __shared__ float As[BM][BK + PADA];
    __shared__ float Bs[BK][BN + PADB];

    const int tid = threadIdx.x;
    const int wid = tid >> 5;
    const int wm = wid >> 1;      // 0..3
    const int wn = wid & 1;       // 0..1

    wmma::fragment<wmma::accumulator, 16, 16, 8, float> acc[2][2];
    #pragma unroll
    for (int i = 0; i < 2; i++)
        #pragma unroll
        for (int j = 0; j < 2; j++)
            wmma::fill_fragment(acc[i][j], 0.0f);

    for (int k0 = 0; k0 < kEnd; k0 += BK) {
        // A tile: 128x16 floats = 512 float4, 2 per thread
        #pragma unroll
        for (int v = tid; v < BM * BK / 4; v += 256) {
            int r = v >> 2, c = (v & 3) << 2;
            *(float4*)&As[r][c] =
                *(const float4*)&A[(long)(i0 + r) * K + k0 + c];
        }
        // B tile: 16x64 floats = 256 float4, 1 per thread
        {
            int r = tid >> 4, c = (tid & 15) << 2;
            *(float4*)&Bs[r][c] =
                *(const float4*)&B[(long)(k0 + r) * N + j0 + c];
        }
        __syncthreads();

        #pragma unroll
        for (int kk = 0; kk < BK; kk += 8) {
            wmma::fragment<wmma::matrix_a, 16, 16, 8, wmma::precision::tf32, wmma::row_major> af[2];
            wmma::fragment<wmma::matrix_b, 16, 16, 8, wmma::precision::tf32, wmma::row_major> bf[2];
            #pragma unroll
            for (int i = 0; i < 2; i++) {
                wmma::load_matrix_sync(af[i], &As[wm * 32 + i * 16][kk], BK + PADA);
                #pragma unroll
                for (int t = 0; t < af[i].num_elements; t++)
                    af[i].x[t] = wmma::__float_to_tf32(af[i].x[t]);
            }
            #pragma unroll
            for (int j = 0; j < 2; j++) {
                wmma::load_matrix_sync(bf[j], &Bs[kk][wn * 32 + j * 16], BN + PADB);
                #pragma unroll
                for (int t = 0; t < bf[j].num_elements; t++)
                    bf[j].x[t] = wmma::__float_to_tf32(bf[j].x[t]);
            }
            #pragma unroll
            for (int i = 0; i < 2; i++)
                #pragma unroll
                for (int j = 0; j < 2; j++)
                    wmma::mma_sync(acc[i][j], af[i], bf[j], acc[i][j]);
        }
        __syncthreads();
    }

    #pragma unroll
    for (int i = 0; i < 2; i++)
        #pragma unroll
        for (int j = 0; j < 2; j++)
            wmma::store_matrix_sync(
                &C[(long)(i0 + wm * 32 + i * 16) * N + j0 + wn * 32 + j * 16],
                acc[i][j], N, wmma::mem_row_major);
}

// ---------------------------------------------------------------------------
// NT GEMM: C[M,N] = alpha * A[M,K] @ B[N,K]^T  (scores = Q @ K^T * scale)
// Skips tiles that are entirely above the causal diagonal.
// ---------------------------------------------------------------------------
__global__ void __launch_bounds__(256) gemm_nt(
    const float* __restrict__ A, const float* __restrict__ B,
    float* __restrict__ C,
    int M, int N, int K,
    long sA, long sB, long sC, float alpha)
{
    const int i0 = blockIdx.y * BM;
    const int j0 = blockIdx.x * BN;
    if (j0 >= i0 + BM) return;   // fully masked tile

    A += (long)blockIdx.z * sA;
    B += (long)blockIdx.z * sB;
    C += (long)blockIdx.z * sC;

    __shared__ float As[BM][BK + PADA];
    __shared__ float Bs[BN][BK + PADA];  // Bs[n][k]

    const int tid = threadIdx.x;
    const int wid = tid >> 5;
    const int wm = wid >> 1;
    const int wn = wid & 1;

    wmma::fragment<wmma::accumulator, 16, 16, 8, float> acc[2][2];
    #pragma unroll
    for (int i = 0; i < 2; i++)
        #pragma unroll
        for (int j = 0; j < 2; j++)
            wmma::fill_fragment(acc[i][j], 0.0f);

    for (int k0 = 0; k0 < K; k0 += BK) {
        #pragma unroll
        for (int v = tid; v < BM * BK / 4; v += 256) {
            int r = v >> 2, c = (v & 3) << 2;
            *(float4*)&As[r][c] =
                *(const float4*)&A[(long)(i0 + r) * K + k0 + c];
        }
        // B tile: 64 rows (n) x 16 floats (k) = 256 float4, 1 per thread
        {
            int r = tid >> 2, c = (tid & 3) << 2;
            *(float4*)&Bs[r][c] =
                *(const float4*)&B[(long)(j0 + r) * K + k0 + c];
        }
        __syncthreads();

        #pragma unroll
        for (int kk = 0; kk < BK; kk += 8) {
            wmma::fragment<wmma::matrix_a, 16, 16, 8, wmma::precision::tf32, wmma::row_major> af[2];
            wmma::fragment<wmma::matrix_b, 16, 16, 8, wmma::precision::tf32, wmma::col_major> bf[2];
            #pragma unroll
            for (int i = 0; i < 2; i++) {
                wmma::load_matrix_sync(af[i], &As[wm * 32 + i * 16][kk], BK + PADA);
                #pragma unroll
                for (int t = 0; t < af[i].num_elements; t++)
                    af[i].x[t] = wmma::__float_to_tf32(af[i].x[t]);
            }
            #pragma unroll
            for (int j = 0; j < 2; j++) {
                // col_major: element (k, n) at Bs[n][k], ld = BK+PADA
                wmma::load_matrix_sync(bf[j], &Bs[wn * 32 + j * 16][kk], BK + PADA);
                #pragma unroll
                for (int t = 0; t < bf[j].num_elements; t++)
                    bf[j].x[t] = wmma::__float_to_tf32(bf[j].x[t]);
            }
            #pragma unroll
            for (int i = 0; i < 2; i++)
                #pragma unroll
                for (int j = 0; j < 2; j++)
                    wmma::mma_sync(acc[i][j], af[i], bf[j], acc[i][j]);
        }
        __syncthreads();
    }

    #pragma unroll
    for (int i = 0; i < 2; i++)
        #pragma unroll
        for (int j = 0; j < 2; j++) {
            #pragma unroll
            for (int t = 0; t < acc[i][j].num_elements; t++)
                acc[i][j].x[t] *= alpha;
            wmma::store_matrix_sync(
                &C[(long)(i0 + wm * 32 + i * 16) * N + j0 + wn * 32 + j * 16],
                acc[i][j], N, wmma::mem_row_major);
        }
}

// ---------------------------------------------------------------------------
// Causal row softmax, in place. One block (256 threads) per row.
// Writes exact zeros for j > i so the PV GEMM can read full tiles.
// ---------------------------------------------------------------------------
__device__ __forceinline__ float blockReduceMax(float v) {
    __shared__ float red[32];
    #pragma unroll
    for (int o = 16; o > 0; o >>= 1) v = fmaxf(v, __shfl_xor_sync(0xffffffffu, v, o));
    int lane = threadIdx.x & 31, wid = threadIdx.x >> 5;
    if (lane == 0) red[wid] = v;
    __syncthreads();
    if (wid == 0) {
        v = (lane < 8) ? red[lane] : -INFINITY;
        #pragma unroll
        for (int o = 4; o > 0; o >>= 1) v = fmaxf(v, __shfl_xor_sync(0xffffffffu, v, o));
        if (lane == 0) red[0] = v;
    }
    __syncthreads();
    v = red[0];
    __syncthreads();
    return v;
}

__device__ __forceinline__ float blockReduceSum(float v) {
    __shared__ float red[32];
    #pragma unroll
    for (int o = 16; o > 0; o >>= 1) v += __shfl_xor_sync(0xffffffffu, v, o);
    int lane = threadIdx.x & 31, wid = threadIdx.x >> 5;
    if (lane == 0) red[wid] = v;
    __syncthreads();
    if (wid == 0) {
        v = (lane < 8) ? red[lane] : 0.0f;
        #pragma unroll
        for (int o = 4; o > 0; o >>= 1) v += __shfl_xor_sync(0xffffffffu, v, o);
        if (lane == 0) red[0] = v;
    }
    __syncthreads();
    v = red[0];
    __syncthreads();
    return v;
}

__global__ void __launch_bounds__(256) softmax_causal(float* __restrict__ S)
{
    const int r = blockIdx.x;          // 0 .. BATCH*SEQ-1
    const int i = r & (SEQ - 1);       // row within batch
    float* row = S + (long)r * SEQ;
    const int tid = threadIdx.x;
    const int valid = i + 1;

    float x[SEQ / 256];
    float m = -INFINITY;
    #pragma unroll
    for (int it = 0; it < SEQ / 256; it++) {
        int j = tid + it * 256;
        x[it] = (j < valid) ? row[j] : -INFINITY;
        m = fmaxf(m, x[it]);
    }
    const float M = blockReduceMax(m);

    float e[SEQ / 256];
    float s = 0.0f;
    #pragma unroll
    for (int it = 0; it < SEQ / 256; it++) {
        int j = tid + it * 256;
        e[it] = (j < valid) ? __expf(x[it] - M) : 0.0f;
        s += e[it];
    }
    const float Ssum = blockReduceSum(s);
    const float inv = 1.0f / Ssum;

    #pragma unroll
    for (int it = 0; it < SEQ / 256; it++) {
        int j = tid + it * 256;
        row[j] = e[it] * inv;   // zeros above diagonal
    }
}

// ---------------------------------------------------------------------------
// Launch
// ---------------------------------------------------------------------------
extern "C" void kernel_launch(void* const* d_in, const int* in_sizes, int n_in,
                              void* d_out, int out_size)
{
    const float* xK = (const float*)d_in[0];
    const float* xV = (const float*)d_in[1];
    const float* xQ = (const float*)d_in[2];
    const float* wK = (const float*)d_in[3];
    const float* wV = (const float*)d_in[4];
    const float* wQ = (const float*)d_in[5];
    float* out = (float*)d_out;

    static float *Qf = nullptr, *Kf = nullptr, *Vf = nullptr, *Sc = nullptr;
    if (!Qf) {
        cudaGetSymbolAddress((void**)&Qf, g_Q);
        cudaGetSymbolAddress((void**)&Kf, g_K);
        cudaGetSymbolAddress((void**)&Vf, g_V);
        cudaGetSymbolAddress((void**)&Sc, g_S);
    }

    const float scale = 1.0f / sqrtf((float)SEQ);
    dim3 blk(256);

    // Projections: [8192,1024] @ [1024,1024]
    dim3 g1(DIM / BN, (BATCH * SEQ) / BM, 1);
    gemm_nn<<<g1, blk>>>(xQ, wQ, Qf, BATCH * SEQ, DIM, DIM, 0, 0, 0, 0);
    gemm_nn<<<g1, blk>>>(xK, wK, Kf, BATCH * SEQ, DIM, DIM, 0, 0, 0, 0);
    gemm_nn<<<g1, blk>>>(xV, wV, Vf, BATCH * SEQ, DIM, DIM, 0, 0, 0, 0);

    // Scores: per batch [2048,1024] @ [2048,1024]^T * scale (causal tiles skipped)
    dim3 g2(SEQ / BN, SEQ / BM, BATCH);
    gemm_nt<<<g2, blk>>>(Qf, Kf, Sc, SEQ, SEQ, DIM,
                         (long)SEQ * DIM, (long)SEQ * DIM, (long)SEQ * SEQ, scale);

    // Softmax (causal, in place)
    softmax_causal<<<BATCH * SEQ, blk>>>(Sc);

    // O = P @ V (k limited per row tile)
    dim3 g3(DIM / BN, SEQ / BM, BATCH);
    gemm_nn<<<g3, blk>>>(Sc, Vf, out, SEQ, DIM, SEQ,
                         (long)SEQ * SEQ, (long)SEQ * DIM, (long)SEQ * DIM, 1);
}

// round 2
// speedup vs baseline: 1.1628x; 1.1628x over previous
#include <cuda_runtime.h>
#include <mma.h>
#include <math.h>

using namespace nvcuda;

#define BATCH 4
#define SEQ   2048
#define DIM   1024

#define BM 128
#define BN 128
#define BKT 32          // k tile
#define LDAS 40         // 128x32 A tile rows padded to 40 floats (160B, 32B-aligned rows)
#define LDBS 136        // 32x128 B tile rows padded to 136 floats (544B, 32B-aligned rows)
#define ABUF (BM * LDAS)         // 5120 floats
#define BBUF_MAX (BM * LDAS)     // NT B tile is 128x40; NN is 32x136=4352 < 5120
#define SMEM_BYTES ((2 * ABUF + 2 * BBUF_MAX) * 4)   // 81920 B

// ---------------- scratch (__device__ globals; allocs forbidden) -----------
__device__ float g_cxQ[(size_t)BATCH * SEQ * DIM];
__device__ float g_cxK[(size_t)BATCH * SEQ * DIM];
__device__ float g_cxV[(size_t)BATCH * SEQ * DIM];
__device__ float g_cwQ[(size_t)DIM * DIM];
__device__ float g_cwK[(size_t)DIM * DIM];
__device__ float g_cwV[(size_t)DIM * DIM];
__device__ float g_Q[(size_t)BATCH * SEQ * DIM];
__device__ float g_K[(size_t)BATCH * SEQ * DIM];
__device__ float g_V[(size_t)BATCH * SEQ * DIM];
__device__ float g_S[(size_t)BATCH * SEQ * SEQ];

// ---------------------------------------------------------------------------
__device__ __forceinline__ void cp16(float* smem, const float* g) {
    unsigned s = (unsigned)__cvta_generic_to_shared(smem);
    asm volatile("cp.async.cg.shared.global [%0], [%1], 16;\n" :: "r"(s), "l"(g));
}
__device__ __forceinline__ void cp_commit() {
    asm volatile("cp.async.commit_group;\n");
}
__device__ __forceinline__ void cp_wait1() {
    asm volatile("cp.async.wait_group 1;\n");
}
__device__ __forceinline__ void cp_wait0() {
    asm volatile("cp.async.wait_group 0;\n");
}

// tf32 rounding pre-pass (round-to-nearest once; GEMMs then never convert)
__global__ void __launch_bounds__(256) cvt_tf32(const float4* __restrict__ in,
                                                float4* __restrict__ out, int n4) {
    int i = blockIdx.x * blockDim.x + threadIdx.x;
    if (i < n4) {
        float4 v = in[i];
        v.x = wmma::__float_to_tf32(v.x);
        v.y = wmma::__float_to_tf32(v.y);
        v.z = wmma::__float_to_tf32(v.z);
        v.w = wmma::__float_to_tf32(v.w);
        out[i] = v;
    }
}

// ---------------------------------------------------------------------------
// Tiled tf32 GEMM. NT: B is [N,K] row-major (compute A @ B^T). Otherwise B is
// [K,N] row-major. ROUND: round output to tf32 (for operands of later GEMMs).
// CMODE: 0 = plain, 1 = skip tiles strictly above causal diagonal (scores),
//        2 = limit k-range to row-tile end (PV; P is exactly 0 above diag).
// ---------------------------------------------------------------------------
template<bool NT, bool ROUND, int CMODE>
__global__ void __launch_bounds__(256, 2) gemm_t(
    const float* __restrict__ A, const float* __restrict__ B,
    float* __restrict__ C, int M, int N, int K,
    long sA, long sB, long sC, float alpha)
{
    const int i0 = blockIdx.y * BM;
    const int j0 = blockIdx.x * BN;
    if (CMODE == 1 && j0 >= i0 + BM) return;

    A += (long)blockIdx.z * sA;
    B += (long)blockIdx.z * sB;
    C += (long)blockIdx.z * sC;

    const int kEnd = (CMODE == 2) ? ((i0 + BM < K) ? i0 + BM : K) : K;
    const int nk = kEnd / BKT;

    extern __shared__ float sm[];
    float* As = sm;
    float* Bs = sm + 2 * ABUF;

    const int tid = threadIdx.x;
    const int wid = tid >> 5;
    const int wm = wid & 1;        // 2 warp rows
    const int wn = wid >> 1;       // 4 warp cols
    const int m_base = wm * 64;
    const int n_base = wn * 32;

    auto load_tiles = [&](int kt, int buf) {
        const int k0 = kt * BKT;
        float* a = As + buf * ABUF;
        #pragma unroll
        for (int i = 0; i < 4; i++) {
            int v = tid + i * 256;
            int r = v >> 3, c = (v & 7) << 2;        // 8 vec4 per 32-float row
            cp16(a + r * LDAS + c, A + (long)(i0 + r) * K + k0 + c);
        }
        float* b = Bs + buf * BBUF_MAX;
        if (NT) {
            #pragma unroll
            for (int i = 0; i < 4; i++) {
                int v = tid + i * 256;
                int r = v >> 3, c = (v & 7) << 2;
                cp16(b + r * LDAS + c, B + (long)(j0 + r) * K + k0 + c);
            }
        } else {
            #pragma unroll
            for (int i = 0; i < 4; i++) {
                int v = tid + i * 256;
                int r = v >> 5, c = (v & 31) << 2;    // 32 vec4 per 128-float row
                cp16(b + r * LDBS + c, B + (long)(k0 + r) * N + j0 + c);
            }
        }
    };

    wmma::fragment<wmma::accumulator, 16, 16, 8, float> acc[4][2];
    #pragma unroll
    for (int i = 0; i < 4; i++)
        #pragma unroll
        for (int j = 0; j < 2; j++)
            wmma::fill_fragment(acc[i][j], 0.0f);

    load_tiles(0, 0);
    cp_commit();

    for (int kt = 0; kt < nk; kt++) {
        if (kt + 1 < nk) {
            load_tiles(kt + 1, (kt + 1) & 1);
            cp_commit();
            cp_wait1();
        } else {
            cp_wait0();
        }
        __syncthreads();

        const float* a = As + (kt & 1) * ABUF;
        const float* b = Bs + (kt & 1) * BBUF_MAX;

        #pragma unroll
        for (int kk = 0; kk < BKT; kk += 8) {
            wmma::fragment<wmma::matrix_a, 16, 16, 8, wmma::precision::tf32, wmma::row_major> af[4];
            #pragma unroll
            for (int i = 0; i < 4; i++)
                wmma::load_matrix_sync(af[i], a + (m_base + i * 16) * LDAS + kk, LDAS);

            if constexpr (NT) {
                wmma::fragment<wmma::matrix_b, 16, 16, 8, wmma::precision::tf32, wmma::col_major> bf[2];
                #pragma unroll
                for (int j = 0; j < 2; j++)
                    wmma::load_matrix_sync(bf[j], b + (n_base + j * 16) * LDAS + kk, LDAS);
                #pragma unroll
                for (int i = 0; i < 4; i++)
                    #pragma unroll
                    for (int j = 0; j < 2; j++)
                        wmma::mma_sync(acc[i][j], af[i], bf[j], acc[i][j]);
            } else {
                wmma::fragment<wmma::matrix_b, 16, 16, 8, wmma::precision::tf32, wmma::row_major> bf[2];
                #pragma unroll
                for (int j = 0; j < 2; j++)
                    wmma::load_matrix_sync(bf[j], b + kk * LDBS + n_base + j * 16, LDBS);
                #pragma unroll
                for (int i = 0; i < 4; i++)
                    #pragma unroll
                    for (int j = 0; j < 2; j++)
                        wmma::mma_sync(acc[i][j], af[i], bf[j], acc[i][j]);
            }
        }
        __syncthreads();
    }

    #pragma unroll
    for (int i = 0; i < 4; i++)
        #pragma unroll
        for (int j = 0; j < 2; j++) {
            #pragma unroll
            for (int t = 0; t < acc[i][j].num_elements; t++) {
                float v = acc[i][j].x[t] * alpha;
                if (ROUND) v = wmma::__float_to_tf32(v);
                acc[i][j].x[t] = v;
            }
            wmma::store_matrix_sync(
                C + (long)(i0 + m_base + i * 16) * N + j0 + n_base + j * 16,
                acc[i][j], N, wmma::mem_row_major);
        }
}

// ---------------------------------------------------------------------------
// Causal row softmax, in place; output rounded to tf32 (it feeds the PV GEMM).
// Exact zeros above the diagonal enable the PV k-limit.
// ---------------------------------------------------------------------------
__device__ __forceinline__ float blockReduceMax(float v) {
    __shared__ float red[32];
    #pragma unroll
    for (int o = 16; o > 0; o >>= 1) v = fmaxf(v, __shfl_xor_sync(0xffffffffu, v, o));
    int lane = threadIdx.x & 31, wid = threadIdx.x >> 5;
    if (lane == 0) red[wid] = v;
    __syncthreads();
    if (wid == 0) {
        v = (lane < 8) ? red[lane] : -INFINITY;
        #pragma unroll
        for (int o = 4; o > 0; o >>= 1) v = fmaxf(v, __shfl_xor_sync(0xffffffffu, v, o));
        if (lane == 0) red[0] = v;
    }
    __syncthreads();
    v = red[0];
    __syncthreads();
    return v;
}
__device__ __forceinline__ float blockReduceSum(float v) {
    __shared__ float red[32];
    #pragma unroll
    for (int o = 16; o > 0; o >>= 1) v += __shfl_xor_sync(0xffffffffu, v, o);
    int lane = threadIdx.x & 31, wid = threadIdx.x >> 5;
    if (lane == 0) red[wid] = v;
    __syncthreads();
    if (wid == 0) {
        v = (lane < 8) ? red[lane] : 0.0f;
        #pragma unroll
        for (int o = 4; o > 0; o >>= 1) v += __shfl_xor_sync(0xffffffffu, v, o);
        if (lane == 0) red[0] = v;
    }
    __syncthreads();
    v = red[0];
    __syncthreads();
    return v;
}

__global__ void __launch_bounds__(256) softmax_causal(float* __restrict__ S)
{
    const int r = blockIdx.x;
    const int i = r & (SEQ - 1);
    float* row = S + (long)r * SEQ;
    const int tid = threadIdx.x;
    const int valid = i + 1;

    float x[SEQ / 256];
    float m = -INFINITY;
    #pragma unroll
    for (int it = 0; it < SEQ / 256; it++) {
        int j = tid + it * 256;
        x[it] = (j < valid) ? row[j] : -INFINITY;
        m = fmaxf(m, x[it]);
    }
    const float M = blockReduceMax(m);

    float e[SEQ / 256];
    float s = 0.0f;
    #pragma unroll
    for (int it = 0; it < SEQ / 256; it++) {
        int j = tid + it * 256;
        e[it] = (j < valid) ? __expf(x[it] - M) : 0.0f;
        s += e[it];
    }
    const float Ssum = blockReduceSum(s);
    const float inv = 1.0f / Ssum;

    #pragma unroll
    for (int it = 0; it < SEQ / 256; it++) {
        int j = tid + it * 256;
        row[j] = wmma::__float_to_tf32(e[it] * inv);   // 0 stays 0 above diag
    }
}

// ---------------------------------------------------------------------------
extern "C" void kernel_launch(void* const* d_in, const int* in_sizes, int n_in,
                              void* d_out, int out_size)
{
    const float* xK = (const float*)d_in[0];
    const float* xV = (const float*)d_in[1];
    const float* xQ = (const float*)d_in[2];
    const float* wK = (const float*)d_in[3];
    const float* wV = (const float*)d_in[4];
    const float* wQ = (const float*)d_in[5];
    float* out = (float*)d_out;

    float *cxQ, *cxK, *cxV, *cwQ, *cwK, *cwV, *Qf, *Kf, *Vf, *Sc;
    cudaGetSymbolAddress((void**)&cxQ, g_cxQ);
    cudaGetSymbolAddress((void**)&cxK, g_cxK);
    cudaGetSymbolAddress((void**)&cxV, g_cxV);
    cudaGetSymbolAddress((void**)&cwQ, g_cwQ);
    cudaGetSymbolAddress((void**)&cwK, g_cwK);
    cudaGetSymbolAddress((void**)&cwV, g_cwV);
    cudaGetSymbolAddress((void**)&Qf, g_Q);
    cudaGetSymbolAddress((void**)&Kf, g_K);
    cudaGetSymbolAddress((void**)&Vf, g_V);
    cudaGetSymbolAddress((void**)&Sc, g_S);

    cudaFuncSetAttribute(gemm_t<false, true, 0>,
                         cudaFuncAttributeMaxDynamicSharedMemorySize, SMEM_BYTES);
    cudaFuncSetAttribute(gemm_t<true, false, 1>,
                         cudaFuncAttributeMaxDynamicSharedMemorySize, SMEM_BYTES);
    cudaFuncSetAttribute(gemm_t<false, false, 2>,
                         cudaFuncAttributeMaxDynamicSharedMemorySize, SMEM_BYTES);

    const float scale = 1.0f / sqrtf((float)SEQ);
    dim3 blk(256);

    // 1) round inputs to tf32 once
    const int nx4 = BATCH * SEQ * DIM / 4;
    const int nw4 = DIM * DIM / 4;
    cvt_tf32<<<(nx4 + 255) / 256, blk>>>((const float4*)xQ, (float4*)cxQ, nx4);
    cvt_tf32<<<(nx4 + 255) / 256, blk>>>((const float4*)xK, (float4*)cxK, nx4);
    cvt_tf32<<<(nx4 + 255) / 256, blk>>>((const float4*)xV, (float4*)cxV, nx4);
    cvt_tf32<<<(nw4 + 255) / 256, blk>>>((const float4*)wQ, (float4*)cwQ, nw4);
    cvt_tf32<<<(nw4 + 255) / 256, blk>>>((const float4*)wK, (float4*)cwK, nw4);
    cvt_tf32<<<(nw4 + 255) / 256, blk>>>((const float4*)wV, (float4*)cwV, nw4);

    // 2) projections (epilogue rounds outputs to tf32)
    dim3 g1(DIM / BN, (BATCH * SEQ) / BM, 1);
    gemm_t<false, true, 0><<<g1, blk, SMEM_BYTES>>>(cxQ, cwQ, Qf, BATCH * SEQ, DIM, DIM, 0, 0, 0, 1.0f);
    gemm_t<false, true, 0><<<g1, blk, SMEM_BYTES>>>(cxK, cwK, Kf, BATCH * SEQ, DIM, DIM, 0, 0, 0, 1.0f);
    gemm_t<false, true, 0><<<g1, blk, SMEM_BYTES>>>(cxV, cwV, Vf, BATCH * SEQ, DIM, DIM, 0, 0, 0, 1.0f);

    // 3) scores = Q @ K^T * scale (upper tiles skipped)
    dim3 g2(SEQ / BN, SEQ / BM, BATCH);
    gemm_t<true, false, 1><<<g2, blk, SMEM_BYTES>>>(Qf, Kf, Sc, SEQ, SEQ, DIM,
        (long)SEQ * DIM, (long)SEQ * DIM, (long)SEQ * SEQ, scale);

    // 4) causal softmax (rounds P to tf32)
    softmax_causal<<<BATCH * SEQ, blk>>>(Sc);

    // 5) O = P @ V  (k limited per row tile)
    dim3 g3(DIM / BN, SEQ / BM, BATCH);
    gemm_t<false, false, 2><<<g3, blk, SMEM_BYTES>>>(Sc, Vf, out, SEQ, DIM, SEQ,
        (long)SEQ * SEQ, (long)SEQ * DIM, (long)SEQ * DIM, 1.0f);
}